// round 5
// baseline (speedup 1.0000x reference)
#include <cuda_runtime.h>

#define N_NODES  50000
#define N_EDGES  800000
#define N_GRAPHS 128
#define D        128

// Scratch (device globals — no allocation allowed)
__device__ float g_hw[N_NODES * D];     // (H @ W) * dinv[row]
__device__ float g_agg[N_NODES * D];    // aggregated layer output
__device__ float g_dinv[N_NODES];
__device__ int   g_ecnt[N_NODES];       // zero-init at load; re-zeroed by scan each replay
__device__ int   g_off[N_NODES + 1];    // CSR offsets (deg = off[i+1]-off[i])
__device__ int   g_cur[N_NODES];        // fill cursors
__device__ int   g_srcs[N_EDGES];       // src node ids, grouped by dst

// ---------------------------------------------------------------------------
// CSR build: histogram -> scan (+dinv, +self-reset) -> fill
// ---------------------------------------------------------------------------
__global__ void hist_kernel(const int* __restrict__ ei, int E) {
    int e = blockIdx.x * blockDim.x + threadIdx.x;
    if (e < E) atomicAdd(&g_ecnt[ei[E + e]], 1);
}

// single block, 1024 threads: exclusive scan over 50000 counts.
// Also zeroes g_ecnt behind itself so the next replay's hist starts clean.
__global__ void scan_kernel(int n) {
    __shared__ int part[1024];
    const int t = threadIdx.x;
    const int chunk = (n + 1023) / 1024;
    const int s = t * chunk;
    const int e = min(s + chunk, n);
    int sum = 0;
    for (int i = s; i < e; i++) sum += g_ecnt[i];
    part[t] = sum;
    __syncthreads();
    for (int d = 1; d < 1024; d <<= 1) {
        int v = (t >= d) ? part[t - d] : 0;
        __syncthreads();
        part[t] += v;
        __syncthreads();
    }
    int run = part[t] - sum;   // exclusive prefix
    for (int i = s; i < e; i++) {
        int c = g_ecnt[i];
        g_ecnt[i] = 0;                        // reset for next replay
        g_off[i] = run;
        g_cur[i] = run;
        g_dinv[i] = rsqrtf((float)(c + 1));   // +1 self-loop
        run += c;
    }
    if (e == n && s < n) g_off[n] = run;      // total
}

__global__ void fill_kernel(const int* __restrict__ ei, int E) {
    int e = blockIdx.x * blockDim.x + threadIdx.x;
    if (e >= E) return;
    int row = ei[e];
    int col = ei[E + e];
    int pos = atomicAdd(&g_cur[col], 1);
    g_srcs[pos] = row;
}

// ---------------------------------------------------------------------------
// packed f32x2 helpers
// ---------------------------------------------------------------------------
__device__ __forceinline__ unsigned long long bcast2(float v) {
    unsigned long long r;
    asm("mov.b64 %0, {%1, %1};" : "=l"(r) : "r"(__float_as_uint(v)));
    return r;
}
__device__ __forceinline__ void fma2(unsigned long long& acc,
                                     unsigned long long a,
                                     unsigned long long b) {
    asm("fma.rn.f32x2 %0, %1, %2, %0;" : "+l"(acc) : "l"(a), "l"(b));
}
__device__ __forceinline__ void mul2(unsigned long long& d,
                                     unsigned long long s) {
    asm("mul.rn.f32x2 %0, %0, %1;" : "+l"(d) : "l"(s));
}

// ---------------------------------------------------------------------------
// GEMM: OUT[r,:] = (act(H)[r,:] @ W) * dinv[r]
// 256 threads, 64 rows/block, 4 rows x 8 cols per thread, fma.rn.f32x2.
// W staged in four 32-k chunks (16KB) + H tile (32KB) = 48KB static smem
// -> 3 blocks/SM (24 warps) for fma-pipe saturation.
// ---------------------------------------------------------------------------
template <bool RELU>
__global__ __launch_bounds__(256, 3) void gemm_kernel(const float* __restrict__ H,
                                                      const float* __restrict__ W,
                                                      float* __restrict__ OUT, int n) {
    __shared__ float sW[32 * D];   // 16KB (one k-chunk)
    __shared__ float sH[64 * D];   // 32KB

    const int tid  = threadIdx.x;
    const int row0 = blockIdx.x * 64;

    // stage H tile (64x128) with optional ReLU
#pragma unroll
    for (int i = 0; i < 8; i++) {
        int idx = (i * 256 + tid) * 4;
        int r   = row0 + (idx >> 7);
        float4 v;
        if (r < n) {
            v = *(const float4*)(H + r * D + (idx & 127));
            if (RELU) {
                v.x = fmaxf(v.x, 0.f); v.y = fmaxf(v.y, 0.f);
                v.z = fmaxf(v.z, 0.f); v.w = fmaxf(v.w, 0.f);
            }
        } else {
            v = make_float4(0.f, 0.f, 0.f, 0.f);
        }
        *(float4*)(sH + idx) = v;
    }

    const int tx = tid & 15;    // col group: 8 cols at tx*8
    const int ty = tid >> 4;    // rows ty*4 .. ty*4+3

    unsigned long long acc[4][4] = {};   // [row][pair], pair p = cols 2p,2p+1

#pragma unroll
    for (int kc = 0; kc < 4; kc++) {
        __syncthreads();   // H staged (kc=0) / previous chunk consumed
        // stage W rows [kc*32, kc*32+32)
#pragma unroll
        for (int i = 0; i < 4; i++) {
            int idx = (i * 256 + tid) * 4;
            *(float4*)(sW + idx) = *(const float4*)(W + kc * 32 * D + idx);
        }
        __syncthreads();

#pragma unroll 2
        for (int k = 0; k < 32; k += 4) {
            int hk = kc * 32 + k;
            float4 h0 = *(float4*)(sH + (ty * 4 + 0) * D + hk);
            float4 h1 = *(float4*)(sH + (ty * 4 + 1) * D + hk);
            float4 h2 = *(float4*)(sH + (ty * 4 + 2) * D + hk);
            float4 h3 = *(float4*)(sH + (ty * 4 + 3) * D + hk);
#pragma unroll
            for (int kk = 0; kk < 4; kk++) {
                const ulonglong2* wr = (const ulonglong2*)(sW + (k + kk) * D + tx * 8);
                ulonglong2 wa = wr[0];
                ulonglong2 wb = wr[1];
                float hv0 = (kk == 0) ? h0.x : (kk == 1) ? h0.y : (kk == 2) ? h0.z : h0.w;
                float hv1 = (kk == 0) ? h1.x : (kk == 1) ? h1.y : (kk == 2) ? h1.z : h1.w;
                float hv2 = (kk == 0) ? h2.x : (kk == 1) ? h2.y : (kk == 2) ? h2.z : h2.w;
                float hv3 = (kk == 0) ? h3.x : (kk == 1) ? h3.y : (kk == 2) ? h3.z : h3.w;
                unsigned long long p0 = bcast2(hv0);
                unsigned long long p1 = bcast2(hv1);
                unsigned long long p2 = bcast2(hv2);
                unsigned long long p3 = bcast2(hv3);
                fma2(acc[0][0], p0, wa.x); fma2(acc[0][1], p0, wa.y);
                fma2(acc[0][2], p0, wb.x); fma2(acc[0][3], p0, wb.y);
                fma2(acc[1][0], p1, wa.x); fma2(acc[1][1], p1, wa.y);
                fma2(acc[1][2], p1, wb.x); fma2(acc[1][3], p1, wb.y);
                fma2(acc[2][0], p2, wa.x); fma2(acc[2][1], p2, wa.y);
                fma2(acc[2][2], p2, wb.x); fma2(acc[2][3], p2, wb.y);
                fma2(acc[3][0], p3, wa.x); fma2(acc[3][1], p3, wa.y);
                fma2(acc[3][2], p3, wb.x); fma2(acc[3][3], p3, wb.y);
            }
        }
    }

    const int col = tx * 8;
#pragma unroll
    for (int i = 0; i < 4; i++) {
        int r = row0 + ty * 4 + i;
        if (r < n) {
            unsigned long long sp = bcast2(g_dinv[r]);
            mul2(acc[i][0], sp); mul2(acc[i][1], sp);
            mul2(acc[i][2], sp); mul2(acc[i][3], sp);
            ulonglong2* o = (ulonglong2*)(OUT + r * D + col);
            o[0] = make_ulonglong2(acc[i][0], acc[i][1]);
            o[1] = make_ulonglong2(acc[i][2], acc[i][3]);
        }
    }
}

// ---------------------------------------------------------------------------
// Gather aggregation (warp per node, float4 per lane):
// agg[i] = dinv[i] * (hw'[i] + sum_in hw'[src]) + b
// ---------------------------------------------------------------------------
__global__ __launch_bounds__(256) void gather_kernel(const float* __restrict__ b, int n) {
    const int node = blockIdx.x * 8 + (threadIdx.x >> 5);
    const int lane = threadIdx.x & 31;
    if (node >= n) return;

    const float4* __restrict__ hw4 = (const float4*)g_hw;
    float4 acc = hw4[node * 32 + lane];   // self term (hw' includes dinv[src])

    const int off = g_off[node];
    const int deg = g_off[node + 1] - off;
    const int* __restrict__ src = g_srcs + off;

    int j = 0;
    for (; j + 4 <= deg; j += 4) {
        int s0 = src[j + 0], s1 = src[j + 1], s2 = src[j + 2], s3 = src[j + 3];
        float4 v0 = __ldg(hw4 + s0 * 32 + lane);
        float4 v1 = __ldg(hw4 + s1 * 32 + lane);
        float4 v2 = __ldg(hw4 + s2 * 32 + lane);
        float4 v3 = __ldg(hw4 + s3 * 32 + lane);
        acc.x += v0.x + v1.x + v2.x + v3.x;
        acc.y += v0.y + v1.y + v2.y + v3.y;
        acc.z += v0.z + v1.z + v2.z + v3.z;
        acc.w += v0.w + v1.w + v2.w + v3.w;
    }
    for (; j < deg; j++) {
        float4 v = __ldg(hw4 + src[j] * 32 + lane);
        acc.x += v.x; acc.y += v.y; acc.z += v.z; acc.w += v.w;
    }

    float s = g_dinv[node];
    float4 bb = ((const float4*)b)[lane];
    float4 out;
    out.x = fmaf(acc.x, s, bb.x);
    out.y = fmaf(acc.y, s, bb.y);
    out.z = fmaf(acc.z, s, bb.z);
    out.w = fmaf(acc.w, s, bb.w);
    ((float4*)g_agg)[node * 32 + lane] = out;
}

// ---------------------------------------------------------------------------
// Fused mean-pool (sorted batch, binary search) + 128->3 head.
// ---------------------------------------------------------------------------
__global__ __launch_bounds__(128) void pool_head_kernel(const int* __restrict__ batch,
                                                        const float* __restrict__ Wlin,
                                                        const float* __restrict__ blin,
                                                        float* __restrict__ out, int n) {
    __shared__ float sp[D];
    __shared__ int bounds[2];
    const int g = blockIdx.x;
    const int c = threadIdx.x;

    if (c < 2) {
        int target = g + c;
        int lo = 0, hi = n;
        while (lo < hi) {
            int m = (lo + hi) >> 1;
            if (batch[m] < target) lo = m + 1; else hi = m;
        }
        bounds[c] = lo;
    }
    __syncthreads();
    const int start = bounds[0], end = bounds[1];

    float acc = 0.f;
    for (int i = start; i < end; i++)
        acc += g_agg[i * D + c];
    float cnt = fmaxf((float)(end - start), 1.f);
    sp[c] = acc / cnt;
    __syncthreads();

    if (c < 3) {
        float a = blin[c];
#pragma unroll 8
        for (int k = 0; k < D; k++)
            a = fmaf(sp[k], Wlin[k * 3 + c], a);
        out[g * 3 + c] = a;
    }
}

// ---------------------------------------------------------------------------
// launch
// ---------------------------------------------------------------------------
extern "C" void kernel_launch(void* const* d_in, const int* in_sizes, int n_in,
                              void* d_out, int out_size) {
    const float* x     = (const float*)d_in[0];
    const int*   ei    = (const int*)  d_in[1];
    const int*   batch = (const int*)  d_in[2];
    const float* W1    = (const float*)d_in[3];
    const float* b1    = (const float*)d_in[4];
    const float* W2    = (const float*)d_in[5];
    const float* b2    = (const float*)d_in[6];
    const float* W3    = (const float*)d_in[7];
    const float* b3    = (const float*)d_in[8];
    const float* Wlin  = (const float*)d_in[9];
    const float* blin  = (const float*)d_in[10];
    float* out = (float*)d_out;

    const int n = in_sizes[0] / D;   // 50000
    const int E = in_sizes[1] / 2;   // 800000

    float* hw_ptr;
    cudaGetSymbolAddress((void**)&hw_ptr, g_hw);
    float* agg_ptr;
    cudaGetSymbolAddress((void**)&agg_ptr, g_agg);

    const int gemm_blocks = (n + 63) / 64;
    const int gath_blocks = (n + 7) / 8;

    // CSR build + normalization (3 launches; launch #3 overall = gemm -> profiled)
    hist_kernel<<<(E + 255) / 256, 256>>>(ei, E);
    scan_kernel<<<1, 1024>>>(n);
    fill_kernel<<<(E + 255) / 256, 256>>>(ei, E);

    // layer 1
    gemm_kernel<false><<<gemm_blocks, 256>>>(x, W1, hw_ptr, n);
    gather_kernel<<<gath_blocks, 256>>>(b1, n);

    // layer 2 (relu fused into GEMM load)
    gemm_kernel<true><<<gemm_blocks, 256>>>(agg_ptr, W2, hw_ptr, n);
    gather_kernel<<<gath_blocks, 256>>>(b2, n);

    // layer 3
    gemm_kernel<true><<<gemm_blocks, 256>>>(agg_ptr, W3, hw_ptr, n);
    gather_kernel<<<gath_blocks, 256>>>(b3, n);

    // fused mean pool + head
    pool_head_kernel<<<N_GRAPHS, D>>>(batch, Wlin, blin, out, n);
}

// round 6
// speedup vs baseline: 1.1791x; 1.1791x over previous
#include <cuda_runtime.h>

#define N_NODES  50000
#define N_EDGES  800000
#define N_GRAPHS 128
#define D        128

// Scratch (device globals — no allocation allowed)
__device__ float g_hw[N_NODES * D];     // (H @ W) * dinv[row]
__device__ float g_agg[N_NODES * D];    // aggregated layer output
__device__ float g_dinv[N_NODES];
__device__ int   g_ecnt[N_NODES];       // zero-init at load; re-zeroed by scan each replay
__device__ int   g_off[N_NODES + 1];    // CSR offsets (deg = off[i+1]-off[i])
__device__ int   g_cur[N_NODES];        // fill cursors
__device__ int   g_srcs[N_EDGES];       // src node ids, grouped by dst

// ---------------------------------------------------------------------------
// CSR build: histogram -> scan (+dinv, +self-reset) -> fill
// ---------------------------------------------------------------------------
__global__ void hist_kernel(const int* __restrict__ ei, int E) {
    int e = blockIdx.x * blockDim.x + threadIdx.x;
    if (e < E) atomicAdd(&g_ecnt[ei[E + e]], 1);
}

// single block, 1024 threads: exclusive scan over 50000 counts.
// Also zeroes g_ecnt behind itself so the next replay's hist starts clean.
__global__ void scan_kernel(int n) {
    __shared__ int part[1024];
    const int t = threadIdx.x;
    const int chunk = (n + 1023) / 1024;
    const int s = t * chunk;
    const int e = min(s + chunk, n);
    int sum = 0;
    for (int i = s; i < e; i++) sum += g_ecnt[i];
    part[t] = sum;
    __syncthreads();
    for (int d = 1; d < 1024; d <<= 1) {
        int v = (t >= d) ? part[t - d] : 0;
        __syncthreads();
        part[t] += v;
        __syncthreads();
    }
    int run = part[t] - sum;   // exclusive prefix
    for (int i = s; i < e; i++) {
        int c = g_ecnt[i];
        g_ecnt[i] = 0;                        // reset for next replay
        g_off[i] = run;
        g_cur[i] = run;
        g_dinv[i] = rsqrtf((float)(c + 1));   // +1 self-loop
        run += c;
    }
    if (e == n && s < n) g_off[n] = run;      // total
}

__global__ void fill_kernel(const int* __restrict__ ei, int E) {
    int e = blockIdx.x * blockDim.x + threadIdx.x;
    if (e >= E) return;
    int row = ei[e];
    int col = ei[E + e];
    int pos = atomicAdd(&g_cur[col], 1);
    g_srcs[pos] = row;
}

// ---------------------------------------------------------------------------
// packed f32x2 helpers
// ---------------------------------------------------------------------------
__device__ __forceinline__ unsigned long long bcast2(float v) {
    unsigned long long r;
    asm("mov.b64 %0, {%1, %1};" : "=l"(r) : "r"(__float_as_uint(v)));
    return r;
}
__device__ __forceinline__ void fma2(unsigned long long& acc,
                                     unsigned long long a,
                                     unsigned long long b) {
    asm("fma.rn.f32x2 %0, %1, %2, %0;" : "+l"(acc) : "l"(a), "l"(b));
}
__device__ __forceinline__ void mul2(unsigned long long& d,
                                     unsigned long long s) {
    asm("mul.rn.f32x2 %0, %0, %1;" : "+l"(d) : "l"(s));
}

// ---------------------------------------------------------------------------
// GEMM: OUT[r,:] = (act(H)[r,:] @ W) * dinv[r]
// 128 threads, 64 rows/block, 8 rows x 8 cols per thread (crossbar-optimal:
// 16 LDS.128 per warp per 4-k group feeds 8192 FMA).
// W staged in four 32-k chunks (16KB) + H tile (32KB) = 48KB static smem.
// ---------------------------------------------------------------------------
template <bool RELU>
__global__ __launch_bounds__(128, 4) void gemm_kernel(const float* __restrict__ H,
                                                      const float* __restrict__ W,
                                                      float* __restrict__ OUT, int n) {
    __shared__ float sW[32 * D];   // 16KB (one k-chunk)
    __shared__ float sH[64 * D];   // 32KB

    const int tid  = threadIdx.x;        // 0..127
    const int row0 = blockIdx.x * 64;

    // stage H tile (64x128) with optional ReLU: 2048 float4, 16 iters
#pragma unroll
    for (int i = 0; i < 16; i++) {
        int idx = (i * 128 + tid) * 4;
        int r   = row0 + (idx >> 7);
        float4 v;
        if (r < n) {
            v = *(const float4*)(H + r * D + (idx & 127));
            if (RELU) {
                v.x = fmaxf(v.x, 0.f); v.y = fmaxf(v.y, 0.f);
                v.z = fmaxf(v.z, 0.f); v.w = fmaxf(v.w, 0.f);
            }
        } else {
            v = make_float4(0.f, 0.f, 0.f, 0.f);
        }
        *(float4*)(sH + idx) = v;
    }

    const int tx = tid & 15;    // col group: 8 cols at tx*8
    const int ty = tid >> 4;    // row group: 8 rows at ty*8

    unsigned long long acc[8][4] = {};   // [row][pair], pair p = cols 2p..2p+1

#pragma unroll
    for (int kc = 0; kc < 4; kc++) {
        __syncthreads();   // H staged (kc=0) / previous chunk consumed
        // stage W rows [kc*32, kc*32+32): 1024 float4, 8 iters
#pragma unroll
        for (int i = 0; i < 8; i++) {
            int idx = (i * 128 + tid) * 4;
            *(float4*)(sW + idx) = *(const float4*)(W + kc * 32 * D + idx);
        }
        __syncthreads();

#pragma unroll 2
        for (int k = 0; k < 32; k += 4) {
            const int hk = kc * 32 + k;
            float4 h[8];
#pragma unroll
            for (int r = 0; r < 8; r++)
                h[r] = *(float4*)(sH + (ty * 8 + r) * D + hk);

#pragma unroll
            for (int kk = 0; kk < 4; kk++) {
                const ulonglong2* wr = (const ulonglong2*)(sW + (k + kk) * D + tx * 8);
                ulonglong2 wa = wr[0];
                ulonglong2 wb = wr[1];
#pragma unroll
                for (int r = 0; r < 8; r++) {
                    float hv = (kk == 0) ? h[r].x : (kk == 1) ? h[r].y
                             : (kk == 2) ? h[r].z : h[r].w;
                    unsigned long long p = bcast2(hv);
                    fma2(acc[r][0], p, wa.x);
                    fma2(acc[r][1], p, wa.y);
                    fma2(acc[r][2], p, wb.x);
                    fma2(acc[r][3], p, wb.y);
                }
            }
        }
    }

    const int col = tx * 8;
#pragma unroll
    for (int i = 0; i < 8; i++) {
        int r = row0 + ty * 8 + i;
        if (r < n) {
            unsigned long long sp = bcast2(g_dinv[r]);
            mul2(acc[i][0], sp); mul2(acc[i][1], sp);
            mul2(acc[i][2], sp); mul2(acc[i][3], sp);
            ulonglong2* o = (ulonglong2*)(OUT + r * D + col);
            o[0] = make_ulonglong2(acc[i][0], acc[i][1]);
            o[1] = make_ulonglong2(acc[i][2], acc[i][3]);
        }
    }
}

// ---------------------------------------------------------------------------
// Gather aggregation (warp per node, float4 per lane, MLP=8):
// agg[i] = dinv[i] * (hw'[i] + sum_in hw'[src]) + b
// ---------------------------------------------------------------------------
__global__ __launch_bounds__(256) void gather_kernel(const float* __restrict__ b, int n) {
    const int node = blockIdx.x * 8 + (threadIdx.x >> 5);
    const int lane = threadIdx.x & 31;
    if (node >= n) return;

    const float4* __restrict__ hw4 = (const float4*)g_hw;
    float4 acc = hw4[node * 32 + lane];   // self term (hw' includes dinv[src])

    const int off = g_off[node];
    const int deg = g_off[node + 1] - off;
    const int* __restrict__ src = g_srcs + off;

    int j = 0;
    for (; j + 8 <= deg; j += 8) {
        int s0 = src[j + 0], s1 = src[j + 1], s2 = src[j + 2], s3 = src[j + 3];
        int s4 = src[j + 4], s5 = src[j + 5], s6 = src[j + 6], s7 = src[j + 7];
        float4 v0 = __ldg(hw4 + s0 * 32 + lane);
        float4 v1 = __ldg(hw4 + s1 * 32 + lane);
        float4 v2 = __ldg(hw4 + s2 * 32 + lane);
        float4 v3 = __ldg(hw4 + s3 * 32 + lane);
        float4 v4 = __ldg(hw4 + s4 * 32 + lane);
        float4 v5 = __ldg(hw4 + s5 * 32 + lane);
        float4 v6 = __ldg(hw4 + s6 * 32 + lane);
        float4 v7 = __ldg(hw4 + s7 * 32 + lane);
        acc.x += (v0.x + v1.x) + (v2.x + v3.x) + ((v4.x + v5.x) + (v6.x + v7.x));
        acc.y += (v0.y + v1.y) + (v2.y + v3.y) + ((v4.y + v5.y) + (v6.y + v7.y));
        acc.z += (v0.z + v1.z) + (v2.z + v3.z) + ((v4.z + v5.z) + (v6.z + v7.z));
        acc.w += (v0.w + v1.w) + (v2.w + v3.w) + ((v4.w + v5.w) + (v6.w + v7.w));
    }
    for (; j + 4 <= deg; j += 4) {
        int s0 = src[j + 0], s1 = src[j + 1], s2 = src[j + 2], s3 = src[j + 3];
        float4 v0 = __ldg(hw4 + s0 * 32 + lane);
        float4 v1 = __ldg(hw4 + s1 * 32 + lane);
        float4 v2 = __ldg(hw4 + s2 * 32 + lane);
        float4 v3 = __ldg(hw4 + s3 * 32 + lane);
        acc.x += (v0.x + v1.x) + (v2.x + v3.x);
        acc.y += (v0.y + v1.y) + (v2.y + v3.y);
        acc.z += (v0.z + v1.z) + (v2.z + v3.z);
        acc.w += (v0.w + v1.w) + (v2.w + v3.w);
    }
    for (; j < deg; j++) {
        float4 v = __ldg(hw4 + src[j] * 32 + lane);
        acc.x += v.x; acc.y += v.y; acc.z += v.z; acc.w += v.w;
    }

    float s = g_dinv[node];
    float4 bb = ((const float4*)b)[lane];
    float4 out;
    out.x = fmaf(acc.x, s, bb.x);
    out.y = fmaf(acc.y, s, bb.y);
    out.z = fmaf(acc.z, s, bb.z);
    out.w = fmaf(acc.w, s, bb.w);
    ((float4*)g_agg)[node * 32 + lane] = out;
}

// ---------------------------------------------------------------------------
// Fused mean-pool (sorted batch, binary search) + 128->3 head.
// ---------------------------------------------------------------------------
__global__ __launch_bounds__(128) void pool_head_kernel(const int* __restrict__ batch,
                                                        const float* __restrict__ Wlin,
                                                        const float* __restrict__ blin,
                                                        float* __restrict__ out, int n) {
    __shared__ float sp[D];
    __shared__ int bounds[2];
    const int g = blockIdx.x;
    const int c = threadIdx.x;

    if (c < 2) {
        int target = g + c;
        int lo = 0, hi = n;
        while (lo < hi) {
            int m = (lo + hi) >> 1;
            if (batch[m] < target) lo = m + 1; else hi = m;
        }
        bounds[c] = lo;
    }
    __syncthreads();
    const int start = bounds[0], end = bounds[1];

    float acc = 0.f;
    for (int i = start; i < end; i++)
        acc += g_agg[i * D + c];
    float cnt = fmaxf((float)(end - start), 1.f);
    sp[c] = acc / cnt;
    __syncthreads();

    if (c < 3) {
        float a = blin[c];
#pragma unroll 8
        for (int k = 0; k < D; k++)
            a = fmaf(sp[k], Wlin[k * 3 + c], a);
        out[g * 3 + c] = a;
    }
}

// ---------------------------------------------------------------------------
// launch
// ---------------------------------------------------------------------------
extern "C" void kernel_launch(void* const* d_in, const int* in_sizes, int n_in,
                              void* d_out, int out_size) {
    const float* x     = (const float*)d_in[0];
    const int*   ei    = (const int*)  d_in[1];
    const int*   batch = (const int*)  d_in[2];
    const float* W1    = (const float*)d_in[3];
    const float* b1    = (const float*)d_in[4];
    const float* W2    = (const float*)d_in[5];
    const float* b2    = (const float*)d_in[6];
    const float* W3    = (const float*)d_in[7];
    const float* b3    = (const float*)d_in[8];
    const float* Wlin  = (const float*)d_in[9];
    const float* blin  = (const float*)d_in[10];
    float* out = (float*)d_out;

    const int n = in_sizes[0] / D;   // 50000
    const int E = in_sizes[1] / 2;   // 800000

    float* hw_ptr;
    cudaGetSymbolAddress((void**)&hw_ptr, g_hw);
    float* agg_ptr;
    cudaGetSymbolAddress((void**)&agg_ptr, g_agg);

    const int gemm_blocks = (n + 63) / 64;
    const int gath_blocks = (n + 7) / 8;

    // CSR build + normalization (launch #4 overall = gemm<false> -> profiled)
    hist_kernel<<<(E + 255) / 256, 256>>>(ei, E);
    scan_kernel<<<1, 1024>>>(n);
    fill_kernel<<<(E + 255) / 256, 256>>>(ei, E);

    // layer 1
    gemm_kernel<false><<<gemm_blocks, 128>>>(x, W1, hw_ptr, n);
    gather_kernel<<<gath_blocks, 256>>>(b1, n);

    // layer 2 (relu fused into GEMM load)
    gemm_kernel<true><<<gemm_blocks, 128>>>(agg_ptr, W2, hw_ptr, n);
    gather_kernel<<<gath_blocks, 256>>>(b2, n);

    // layer 3
    gemm_kernel<true><<<gemm_blocks, 128>>>(agg_ptr, W3, hw_ptr, n);
    gather_kernel<<<gath_blocks, 256>>>(b3, n);

    // fused mean pool + head
    pool_head_kernel<<<N_GRAPHS, D>>>(batch, Wlin, blin, out, n);
}

// round 7
// speedup vs baseline: 1.2973x; 1.1002x over previous
#include <cuda_runtime.h>

#define N_NODES  50000
#define N_EDGES  800000
#define N_GRAPHS 128
#define D        128

// Scratch (device globals — no allocation allowed)
__device__ float g_hw[N_NODES * D];     // (H @ W) * dinv[row]
__device__ float g_agg[N_NODES * D];    // aggregated layer output
__device__ float4 g_z[N_NODES];         // layer-3 folded features (3 used)
__device__ float4 g_zagg[N_NODES];      // aggregated layer-3 output
__device__ float g_dinv[N_NODES];
__device__ int   g_ecnt[N_NODES];       // zero-init; re-zeroed by scan each replay
__device__ int   g_off[N_NODES + 1];    // CSR offsets
__device__ int   g_cur[N_NODES];        // fill cursors
__device__ int   g_srcs[N_EDGES];       // src node ids, grouped by dst
__device__ float4 g_wfold[D];           // W3 @ Wlin rows (xyz used)
__device__ float4 g_bfold;              // b3 @ Wlin + blin

// ---------------------------------------------------------------------------
// Fold W3@Wlin and b3@Wlin+blin  (one block, 128 threads)
// ---------------------------------------------------------------------------
__global__ void fold_kernel(const float* __restrict__ W3,
                            const float* __restrict__ b3,
                            const float* __restrict__ Wlin,
                            const float* __restrict__ blin) {
    const int r = threadIdx.x;   // 0..127
    float a0 = 0.f, a1 = 0.f, a2 = 0.f;
#pragma unroll 8
    for (int k = 0; k < D; k++) {
        float w = W3[r * D + k];
        a0 = fmaf(w, Wlin[k * 3 + 0], a0);
        a1 = fmaf(w, Wlin[k * 3 + 1], a1);
        a2 = fmaf(w, Wlin[k * 3 + 2], a2);
    }
    g_wfold[r] = make_float4(a0, a1, a2, 0.f);
    if (r == 0) {
        float c0 = blin[0], c1 = blin[1], c2 = blin[2];
        for (int k = 0; k < D; k++) {
            float b = b3[k];
            c0 = fmaf(b, Wlin[k * 3 + 0], c0);
            c1 = fmaf(b, Wlin[k * 3 + 1], c1);
            c2 = fmaf(b, Wlin[k * 3 + 2], c2);
        }
        g_bfold = make_float4(c0, c1, c2, 0.f);
    }
}

// ---------------------------------------------------------------------------
// CSR build: histogram -> scan (+dinv, +self-reset) -> fill
// ---------------------------------------------------------------------------
__global__ void hist_kernel(const int* __restrict__ ei, int E) {
    int e = blockIdx.x * blockDim.x + threadIdx.x;
    if (e < E) atomicAdd(&g_ecnt[ei[E + e]], 1);
}

__global__ void scan_kernel(int n) {
    __shared__ int part[1024];
    const int t = threadIdx.x;
    const int chunk = (n + 1023) / 1024;
    const int s = t * chunk;
    const int e = min(s + chunk, n);
    int sum = 0;
    for (int i = s; i < e; i++) sum += g_ecnt[i];
    part[t] = sum;
    __syncthreads();
    for (int d = 1; d < 1024; d <<= 1) {
        int v = (t >= d) ? part[t - d] : 0;
        __syncthreads();
        part[t] += v;
        __syncthreads();
    }
    int run = part[t] - sum;
    for (int i = s; i < e; i++) {
        int c = g_ecnt[i];
        g_ecnt[i] = 0;                        // reset for next replay
        g_off[i] = run;
        g_cur[i] = run;
        g_dinv[i] = rsqrtf((float)(c + 1));   // +1 self-loop
        run += c;
    }
    if (e == n && s < n) g_off[n] = run;
}

__global__ void fill_kernel(const int* __restrict__ ei, int E) {
    int e = blockIdx.x * blockDim.x + threadIdx.x;
    if (e >= E) return;
    int row = ei[e];
    int col = ei[E + e];
    int pos = atomicAdd(&g_cur[col], 1);
    g_srcs[pos] = row;
}

// ---------------------------------------------------------------------------
// packed f32x2 helpers
// ---------------------------------------------------------------------------
__device__ __forceinline__ unsigned long long bcast2(float v) {
    unsigned long long r;
    asm("mov.b64 %0, {%1, %1};" : "=l"(r) : "r"(__float_as_uint(v)));
    return r;
}
__device__ __forceinline__ void fma2(unsigned long long& acc,
                                     unsigned long long a,
                                     unsigned long long b) {
    asm("fma.rn.f32x2 %0, %1, %2, %0;" : "+l"(acc) : "l"(a), "l"(b));
}
__device__ __forceinline__ void mul2(unsigned long long& d,
                                     unsigned long long s) {
    asm("mul.rn.f32x2 %0, %0, %1;" : "+l"(d) : "l"(s));
}

// ---------------------------------------------------------------------------
// GEMM: OUT[r,:] = (act(H)[r,:] @ W) * dinv[r]   (layers 1-2)
// 128 threads, 64 rows/block, 8x8 per thread (crossbar-balanced).
// ---------------------------------------------------------------------------
template <bool RELU>
__global__ __launch_bounds__(128, 4) void gemm_kernel(const float* __restrict__ H,
                                                      const float* __restrict__ W,
                                                      float* __restrict__ OUT, int n) {
    __shared__ float sW[32 * D];   // 16KB (one k-chunk)
    __shared__ float sH[64 * D];   // 32KB

    const int tid  = threadIdx.x;
    const int row0 = blockIdx.x * 64;

#pragma unroll
    for (int i = 0; i < 16; i++) {
        int idx = (i * 128 + tid) * 4;
        int r   = row0 + (idx >> 7);
        float4 v;
        if (r < n) {
            v = *(const float4*)(H + r * D + (idx & 127));
            if (RELU) {
                v.x = fmaxf(v.x, 0.f); v.y = fmaxf(v.y, 0.f);
                v.z = fmaxf(v.z, 0.f); v.w = fmaxf(v.w, 0.f);
            }
        } else {
            v = make_float4(0.f, 0.f, 0.f, 0.f);
        }
        *(float4*)(sH + idx) = v;
    }

    const int tx = tid & 15;
    const int ty = tid >> 4;

    unsigned long long acc[8][4] = {};

#pragma unroll
    for (int kc = 0; kc < 4; kc++) {
        __syncthreads();
#pragma unroll
        for (int i = 0; i < 8; i++) {
            int idx = (i * 128 + tid) * 4;
            *(float4*)(sW + idx) = *(const float4*)(W + kc * 32 * D + idx);
        }
        __syncthreads();

#pragma unroll 2
        for (int k = 0; k < 32; k += 4) {
            const int hk = kc * 32 + k;
            float4 h[8];
#pragma unroll
            for (int r = 0; r < 8; r++)
                h[r] = *(float4*)(sH + (ty * 8 + r) * D + hk);

#pragma unroll
            for (int kk = 0; kk < 4; kk++) {
                const ulonglong2* wr = (const ulonglong2*)(sW + (k + kk) * D + tx * 8);
                ulonglong2 wa = wr[0];
                ulonglong2 wb = wr[1];
#pragma unroll
                for (int r = 0; r < 8; r++) {
                    float hv = (kk == 0) ? h[r].x : (kk == 1) ? h[r].y
                             : (kk == 2) ? h[r].z : h[r].w;
                    unsigned long long p = bcast2(hv);
                    fma2(acc[r][0], p, wa.x);
                    fma2(acc[r][1], p, wa.y);
                    fma2(acc[r][2], p, wb.x);
                    fma2(acc[r][3], p, wb.y);
                }
            }
        }
    }

    const int col = tx * 8;
#pragma unroll
    for (int i = 0; i < 8; i++) {
        int r = row0 + ty * 8 + i;
        if (r < n) {
            unsigned long long sp = bcast2(g_dinv[r]);
            mul2(acc[i][0], sp); mul2(acc[i][1], sp);
            mul2(acc[i][2], sp); mul2(acc[i][3], sp);
            ulonglong2* o = (ulonglong2*)(OUT + r * D + col);
            o[0] = make_ulonglong2(acc[i][0], acc[i][1]);
            o[1] = make_ulonglong2(acc[i][2], acc[i][3]);
        }
    }
}

// ---------------------------------------------------------------------------
// Gather aggregation (warp per node, float4 per lane, MLP=8):
// agg[i] = dinv[i] * (hw'[i] + sum_in hw'[src]) + b
// ---------------------------------------------------------------------------
__global__ __launch_bounds__(256) void gather_kernel(const float* __restrict__ b, int n) {
    const int node = blockIdx.x * 8 + (threadIdx.x >> 5);
    const int lane = threadIdx.x & 31;
    if (node >= n) return;

    const float4* __restrict__ hw4 = (const float4*)g_hw;
    float4 acc = hw4[node * 32 + lane];

    const int off = g_off[node];
    const int deg = g_off[node + 1] - off;
    const int* __restrict__ src = g_srcs + off;

    int j = 0;
    for (; j + 8 <= deg; j += 8) {
        int s0 = src[j + 0], s1 = src[j + 1], s2 = src[j + 2], s3 = src[j + 3];
        int s4 = src[j + 4], s5 = src[j + 5], s6 = src[j + 6], s7 = src[j + 7];
        float4 v0 = __ldg(hw4 + s0 * 32 + lane);
        float4 v1 = __ldg(hw4 + s1 * 32 + lane);
        float4 v2 = __ldg(hw4 + s2 * 32 + lane);
        float4 v3 = __ldg(hw4 + s3 * 32 + lane);
        float4 v4 = __ldg(hw4 + s4 * 32 + lane);
        float4 v5 = __ldg(hw4 + s5 * 32 + lane);
        float4 v6 = __ldg(hw4 + s6 * 32 + lane);
        float4 v7 = __ldg(hw4 + s7 * 32 + lane);
        acc.x += (v0.x + v1.x) + (v2.x + v3.x) + ((v4.x + v5.x) + (v6.x + v7.x));
        acc.y += (v0.y + v1.y) + (v2.y + v3.y) + ((v4.y + v5.y) + (v6.y + v7.y));
        acc.z += (v0.z + v1.z) + (v2.z + v3.z) + ((v4.z + v5.z) + (v6.z + v7.z));
        acc.w += (v0.w + v1.w) + (v2.w + v3.w) + ((v4.w + v5.w) + (v6.w + v7.w));
    }
    for (; j + 4 <= deg; j += 4) {
        int s0 = src[j + 0], s1 = src[j + 1], s2 = src[j + 2], s3 = src[j + 3];
        float4 v0 = __ldg(hw4 + s0 * 32 + lane);
        float4 v1 = __ldg(hw4 + s1 * 32 + lane);
        float4 v2 = __ldg(hw4 + s2 * 32 + lane);
        float4 v3 = __ldg(hw4 + s3 * 32 + lane);
        acc.x += (v0.x + v1.x) + (v2.x + v3.x);
        acc.y += (v0.y + v1.y) + (v2.y + v3.y);
        acc.z += (v0.z + v1.z) + (v2.z + v3.z);
        acc.w += (v0.w + v1.w) + (v2.w + v3.w);
    }
    for (; j < deg; j++) {
        float4 v = __ldg(hw4 + src[j] * 32 + lane);
        acc.x += v.x; acc.y += v.y; acc.z += v.z; acc.w += v.w;
    }

    float s = g_dinv[node];
    float4 bb = ((const float4*)b)[lane];
    float4 out;
    out.x = fmaf(acc.x, s, bb.x);
    out.y = fmaf(acc.y, s, bb.y);
    out.z = fmaf(acc.z, s, bb.z);
    out.w = fmaf(acc.w, s, bb.w);
    ((float4*)g_agg)[node * 32 + lane] = out;
}

// ---------------------------------------------------------------------------
// GEMM3 (folded): z[i] = dinv[i] * (relu(h2[i]) @ Wfold)   [N,3 in float4]
// One warp per node; Wfold in smem; shfl butterfly reduce.
// ---------------------------------------------------------------------------
__global__ __launch_bounds__(256) void gemm3_kernel(const float* __restrict__ H, int n) {
    __shared__ float4 swf[D];
    const int tid  = threadIdx.x;
    if (tid < D) swf[tid] = g_wfold[tid];
    if (tid + 128 < D) swf[tid + 128] = g_wfold[tid + 128];
    __syncthreads();

    const int node = blockIdx.x * 8 + (tid >> 5);
    const int lane = tid & 31;
    if (node >= n) return;

    float4 h = *(const float4*)(H + node * D + lane * 4);
    h.x = fmaxf(h.x, 0.f); h.y = fmaxf(h.y, 0.f);
    h.z = fmaxf(h.z, 0.f); h.w = fmaxf(h.w, 0.f);

    float4 w0 = swf[lane * 4 + 0];
    float4 w1 = swf[lane * 4 + 1];
    float4 w2 = swf[lane * 4 + 2];
    float4 w3 = swf[lane * 4 + 3];

    float a0 = h.x * w0.x + h.y * w1.x + h.z * w2.x + h.w * w3.x;
    float a1 = h.x * w0.y + h.y * w1.y + h.z * w2.y + h.w * w3.y;
    float a2 = h.x * w0.z + h.y * w1.z + h.z * w2.z + h.w * w3.z;

#pragma unroll
    for (int m = 16; m > 0; m >>= 1) {
        a0 += __shfl_xor_sync(0xffffffff, a0, m);
        a1 += __shfl_xor_sync(0xffffffff, a1, m);
        a2 += __shfl_xor_sync(0xffffffff, a2, m);
    }
    if (lane == 0) {
        float s = g_dinv[node];
        g_z[node] = make_float4(a0 * s, a1 * s, a2 * s, 0.f);
    }
}

// ---------------------------------------------------------------------------
// gather3: zagg[i] = dinv[i] * (z[i] + sum_in z[src])   (thread per node)
// ---------------------------------------------------------------------------
__global__ __launch_bounds__(256) void gather3_kernel(int n) {
    const int node = blockIdx.x * blockDim.x + threadIdx.x;
    if (node >= n) return;

    float4 zv = g_z[node];
    float a0 = zv.x, a1 = zv.y, a2 = zv.z;

    const int off = g_off[node];
    const int deg = g_off[node + 1] - off;
    const int* __restrict__ src = g_srcs + off;

    int j = 0;
    for (; j + 4 <= deg; j += 4) {
        float4 v0 = __ldg(&g_z[src[j + 0]]);
        float4 v1 = __ldg(&g_z[src[j + 1]]);
        float4 v2 = __ldg(&g_z[src[j + 2]]);
        float4 v3 = __ldg(&g_z[src[j + 3]]);
        a0 += (v0.x + v1.x) + (v2.x + v3.x);
        a1 += (v0.y + v1.y) + (v2.y + v3.y);
        a2 += (v0.z + v1.z) + (v2.z + v3.z);
    }
    for (; j < deg; j++) {
        float4 v = __ldg(&g_z[src[j]]);
        a0 += v.x; a1 += v.y; a2 += v.z;
    }
    float s = g_dinv[node];
    g_zagg[node] = make_float4(a0 * s, a1 * s, a2 * s, 0.f);
}

// ---------------------------------------------------------------------------
// pool: out[g] = mean over batch-range of zagg + bfold   (1 warp per graph)
// ---------------------------------------------------------------------------
__global__ __launch_bounds__(32) void pool_kernel(const int* __restrict__ batch,
                                                  float* __restrict__ out, int n) {
    const int g = blockIdx.x;
    const int lane = threadIdx.x;

    int target = g + (lane & 1);   // lanes 0/1 compute start/end
    int lo = 0, hi = n;
    while (lo < hi) {
        int m = (lo + hi) >> 1;
        if (batch[m] < target) lo = m + 1; else hi = m;
    }
    int start = __shfl_sync(0xffffffff, lo, 0);
    int end   = __shfl_sync(0xffffffff, lo, 1);

    float a0 = 0.f, a1 = 0.f, a2 = 0.f;
    for (int i = start + lane; i < end; i += 32) {
        float4 v = g_zagg[i];
        a0 += v.x; a1 += v.y; a2 += v.z;
    }
#pragma unroll
    for (int m = 16; m > 0; m >>= 1) {
        a0 += __shfl_xor_sync(0xffffffff, a0, m);
        a1 += __shfl_xor_sync(0xffffffff, a1, m);
        a2 += __shfl_xor_sync(0xffffffff, a2, m);
    }
    if (lane == 0) {
        float inv = 1.f / fmaxf((float)(end - start), 1.f);
        float4 bf = g_bfold;
        out[g * 3 + 0] = fmaf(a0, inv, bf.x);
        out[g * 3 + 1] = fmaf(a1, inv, bf.y);
        out[g * 3 + 2] = fmaf(a2, inv, bf.z);
    }
}

// ---------------------------------------------------------------------------
// launch
// ---------------------------------------------------------------------------
extern "C" void kernel_launch(void* const* d_in, const int* in_sizes, int n_in,
                              void* d_out, int out_size) {
    const float* x     = (const float*)d_in[0];
    const int*   ei    = (const int*)  d_in[1];
    const int*   batch = (const int*)  d_in[2];
    const float* W1    = (const float*)d_in[3];
    const float* b1    = (const float*)d_in[4];
    const float* W2    = (const float*)d_in[5];
    const float* b2    = (const float*)d_in[6];
    const float* W3    = (const float*)d_in[7];
    const float* b3    = (const float*)d_in[8];
    const float* Wlin  = (const float*)d_in[9];
    const float* blin  = (const float*)d_in[10];
    float* out = (float*)d_out;

    const int n = in_sizes[0] / D;   // 50000
    const int E = in_sizes[1] / 2;   // 800000

    float* hw_ptr;
    cudaGetSymbolAddress((void**)&hw_ptr, g_hw);
    float* agg_ptr;
    cudaGetSymbolAddress((void**)&agg_ptr, g_agg);

    const int gemm_blocks = (n + 63) / 64;
    const int gath_blocks = (n + 7) / 8;

    // CSR build + weight folding
    hist_kernel<<<(E + 255) / 256, 256>>>(ei, E);
    scan_kernel<<<1, 1024>>>(n);
    fill_kernel<<<(E + 255) / 256, 256>>>(ei, E);
    fold_kernel<<<1, 128>>>(W3, b3, Wlin, blin);

    // layer 1
    gemm_kernel<false><<<gemm_blocks, 128>>>(x, W1, hw_ptr, n);
    gather_kernel<<<gath_blocks, 256>>>(b1, n);

    // layer 2 (relu fused into GEMM load)
    gemm_kernel<true><<<gemm_blocks, 128>>>(agg_ptr, W2, hw_ptr, n);
    gather_kernel<<<gath_blocks, 256>>>(b2, n);

    // layer 3 folded with head: [N,128] @ [128,3]
    gemm3_kernel<<<gath_blocks, 256>>>(agg_ptr, n);
    gather3_kernel<<<(n + 255) / 256, 256>>>(n);

    // mean pool + bias
    pool_kernel<<<N_GRAPHS, 32>>>(batch, out, n);
}

// round 8
// speedup vs baseline: 1.3350x; 1.0291x over previous
#include <cuda_runtime.h>

#define N_NODES  50000
#define N_EDGES  800000
#define N_GRAPHS 128
#define D        128

// Scratch (device globals — no allocation allowed)
__device__ float g_hw[N_NODES * D];     // (H @ W) * dinv[row]
__device__ float g_agg[N_NODES * D];    // aggregated layer output
__device__ float4 g_z[N_NODES];         // layer-3 folded features (3 used)
__device__ float4 g_zagg[N_NODES];      // aggregated layer-3 output
__device__ float g_dinv[N_NODES];
__device__ int   g_ecnt[N_NODES];       // zero-init; re-zeroed by scan each replay
__device__ int   g_off[N_NODES + 1];    // CSR offsets
__device__ int   g_cur[N_NODES];        // fill cursors
__device__ int   g_srcs[N_EDGES];       // src node ids, grouped by dst
__device__ float4 g_wfold[D];           // W3 @ Wlin rows (xyz used)
__device__ float4 g_bfold;              // b3 @ Wlin + blin

// ---------------------------------------------------------------------------
// Fold W3@Wlin (+ b3@Wlin+blin): 129 blocks x 32 threads, shfl reduce.
// ---------------------------------------------------------------------------
__global__ __launch_bounds__(32) void fold_kernel(const float* __restrict__ W3,
                                                  const float* __restrict__ b3,
                                                  const float* __restrict__ Wlin,
                                                  const float* __restrict__ blin) {
    const int r    = blockIdx.x;     // 0..127 rows, 128 = bias
    const int lane = threadIdx.x;
    float a0 = 0.f, a1 = 0.f, a2 = 0.f;
    if (r < D) {
#pragma unroll
        for (int k = lane; k < D; k += 32) {
            float w = W3[r * D + k];
            a0 = fmaf(w, Wlin[k * 3 + 0], a0);
            a1 = fmaf(w, Wlin[k * 3 + 1], a1);
            a2 = fmaf(w, Wlin[k * 3 + 2], a2);
        }
    } else {
#pragma unroll
        for (int k = lane; k < D; k += 32) {
            float b = b3[k];
            a0 = fmaf(b, Wlin[k * 3 + 0], a0);
            a1 = fmaf(b, Wlin[k * 3 + 1], a1);
            a2 = fmaf(b, Wlin[k * 3 + 2], a2);
        }
    }
#pragma unroll
    for (int m = 16; m > 0; m >>= 1) {
        a0 += __shfl_xor_sync(0xffffffff, a0, m);
        a1 += __shfl_xor_sync(0xffffffff, a1, m);
        a2 += __shfl_xor_sync(0xffffffff, a2, m);
    }
    if (lane == 0) {
        if (r < D) g_wfold[r] = make_float4(a0, a1, a2, 0.f);
        else       g_bfold   = make_float4(a0 + blin[0], a1 + blin[1], a2 + blin[2], 0.f);
    }
}

// ---------------------------------------------------------------------------
// CSR build: histogram -> scan (+dinv, +self-reset) -> fill
// ---------------------------------------------------------------------------
__global__ void hist_kernel(const int* __restrict__ ei, int E) {
    int e = blockIdx.x * blockDim.x + threadIdx.x;
    if (e < E) atomicAdd(&g_ecnt[ei[E + e]], 1);
}

__global__ void scan_kernel(int n) {
    __shared__ int part[1024];
    const int t = threadIdx.x;
    const int chunk = (n + 1023) / 1024;
    const int s = t * chunk;
    const int e = min(s + chunk, n);
    int sum = 0;
    for (int i = s; i < e; i++) sum += g_ecnt[i];
    part[t] = sum;
    __syncthreads();
    for (int d = 1; d < 1024; d <<= 1) {
        int v = (t >= d) ? part[t - d] : 0;
        __syncthreads();
        part[t] += v;
        __syncthreads();
    }
    int run = part[t] - sum;
    for (int i = s; i < e; i++) {
        int c = g_ecnt[i];
        g_ecnt[i] = 0;                        // reset for next replay
        g_off[i] = run;
        g_cur[i] = run;
        g_dinv[i] = rsqrtf((float)(c + 1));   // +1 self-loop
        run += c;
    }
    if (e == n && s < n) g_off[n] = run;
}

__global__ void fill_kernel(const int* __restrict__ ei, int E) {
    int e = blockIdx.x * blockDim.x + threadIdx.x;
    if (e >= E) return;
    int row = ei[e];
    int col = ei[E + e];
    int pos = atomicAdd(&g_cur[col], 1);
    g_srcs[pos] = row;
}

// ---------------------------------------------------------------------------
// packed f32x2 helpers
// ---------------------------------------------------------------------------
__device__ __forceinline__ unsigned long long bcast2(float v) {
    unsigned long long r;
    asm("mov.b64 %0, {%1, %1};" : "=l"(r) : "r"(__float_as_uint(v)));
    return r;
}
__device__ __forceinline__ void fma2(unsigned long long& acc,
                                     unsigned long long a,
                                     unsigned long long b) {
    asm("fma.rn.f32x2 %0, %1, %2, %0;" : "+l"(acc) : "l"(a), "l"(b));
}
__device__ __forceinline__ void mul2(unsigned long long& d,
                                     unsigned long long s) {
    asm("mul.rn.f32x2 %0, %0, %1;" : "+l"(d) : "l"(s));
}

// ---------------------------------------------------------------------------
// GEMM: OUT[r,:] = (act(H)[r,:] @ W) * dinv[r]   (layers 1-2)
// 64 threads, 32-row tiles (fine-grained to kill wave quantization),
// 8 rows x 8 cols per thread. smem 32KB -> 7 blocks/SM.
// ---------------------------------------------------------------------------
template <bool RELU>
__global__ __launch_bounds__(64, 7) void gemm_kernel(const float* __restrict__ H,
                                                     const float* __restrict__ W,
                                                     float* __restrict__ OUT, int n) {
    __shared__ float sW[32 * D];   // 16KB (one k-chunk)
    __shared__ float sH[32 * D];   // 16KB

    const int tid  = threadIdx.x;        // 0..63
    const int row0 = blockIdx.x * 32;

    // stage H tile (32x128) with optional ReLU: 1024 float4 / 64 thr = 16 iters
#pragma unroll
    for (int i = 0; i < 16; i++) {
        int idx = (i * 64 + tid) * 4;
        int r   = row0 + (idx >> 7);
        float4 v;
        if (r < n) {
            v = *(const float4*)(H + r * D + (idx & 127));
            if (RELU) {
                v.x = fmaxf(v.x, 0.f); v.y = fmaxf(v.y, 0.f);
                v.z = fmaxf(v.z, 0.f); v.w = fmaxf(v.w, 0.f);
            }
        } else {
            v = make_float4(0.f, 0.f, 0.f, 0.f);
        }
        *(float4*)(sH + idx) = v;
    }

    const int tx = tid & 15;    // col group: 8 cols at tx*8
    const int ty = tid >> 4;    // row group: 8 rows at ty*8 (0..3)

    unsigned long long acc[8][4] = {};

#pragma unroll
    for (int kc = 0; kc < 4; kc++) {
        __syncthreads();
        // stage W rows [kc*32, kc*32+32): 1024 float4 / 64 thr = 16 iters
#pragma unroll
        for (int i = 0; i < 16; i++) {
            int idx = (i * 64 + tid) * 4;
            *(float4*)(sW + idx) = *(const float4*)(W + kc * 32 * D + idx);
        }
        __syncthreads();

#pragma unroll 2
        for (int k = 0; k < 32; k += 4) {
            const int hk = kc * 32 + k;
            float4 h[8];
#pragma unroll
            for (int r = 0; r < 8; r++)
                h[r] = *(float4*)(sH + (ty * 8 + r) * D + hk);

#pragma unroll
            for (int kk = 0; kk < 4; kk++) {
                const ulonglong2* wr = (const ulonglong2*)(sW + (k + kk) * D + tx * 8);
                ulonglong2 wa = wr[0];
                ulonglong2 wb = wr[1];
#pragma unroll
                for (int r = 0; r < 8; r++) {
                    float hv = (kk == 0) ? h[r].x : (kk == 1) ? h[r].y
                             : (kk == 2) ? h[r].z : h[r].w;
                    unsigned long long p = bcast2(hv);
                    fma2(acc[r][0], p, wa.x);
                    fma2(acc[r][1], p, wa.y);
                    fma2(acc[r][2], p, wb.x);
                    fma2(acc[r][3], p, wb.y);
                }
            }
        }
    }

    const int col = tx * 8;
#pragma unroll
    for (int i = 0; i < 8; i++) {
        int r = row0 + ty * 8 + i;
        if (r < n) {
            unsigned long long sp = bcast2(g_dinv[r]);
            mul2(acc[i][0], sp); mul2(acc[i][1], sp);
            mul2(acc[i][2], sp); mul2(acc[i][3], sp);
            ulonglong2* o = (ulonglong2*)(OUT + r * D + col);
            o[0] = make_ulonglong2(acc[i][0], acc[i][1]);
            o[1] = make_ulonglong2(acc[i][2], acc[i][3]);
        }
    }
}

// ---------------------------------------------------------------------------
// Gather aggregation (warp per node, float4 per lane, MLP=8):
// agg[i] = dinv[i] * (hw'[i] + sum_in hw'[src]) + b
// ---------------------------------------------------------------------------
__global__ __launch_bounds__(256) void gather_kernel(const float* __restrict__ b, int n) {
    const int node = blockIdx.x * 8 + (threadIdx.x >> 5);
    const int lane = threadIdx.x & 31;
    if (node >= n) return;

    const float4* __restrict__ hw4 = (const float4*)g_hw;
    float4 acc = hw4[node * 32 + lane];

    const int off = g_off[node];
    const int deg = g_off[node + 1] - off;
    const int* __restrict__ src = g_srcs + off;

    int j = 0;
    for (; j + 8 <= deg; j += 8) {
        int s0 = src[j + 0], s1 = src[j + 1], s2 = src[j + 2], s3 = src[j + 3];
        int s4 = src[j + 4], s5 = src[j + 5], s6 = src[j + 6], s7 = src[j + 7];
        float4 v0 = __ldg(hw4 + s0 * 32 + lane);
        float4 v1 = __ldg(hw4 + s1 * 32 + lane);
        float4 v2 = __ldg(hw4 + s2 * 32 + lane);
        float4 v3 = __ldg(hw4 + s3 * 32 + lane);
        float4 v4 = __ldg(hw4 + s4 * 32 + lane);
        float4 v5 = __ldg(hw4 + s5 * 32 + lane);
        float4 v6 = __ldg(hw4 + s6 * 32 + lane);
        float4 v7 = __ldg(hw4 + s7 * 32 + lane);
        acc.x += (v0.x + v1.x) + (v2.x + v3.x) + ((v4.x + v5.x) + (v6.x + v7.x));
        acc.y += (v0.y + v1.y) + (v2.y + v3.y) + ((v4.y + v5.y) + (v6.y + v7.y));
        acc.z += (v0.z + v1.z) + (v2.z + v3.z) + ((v4.z + v5.z) + (v6.z + v7.z));
        acc.w += (v0.w + v1.w) + (v2.w + v3.w) + ((v4.w + v5.w) + (v6.w + v7.w));
    }
    for (; j + 4 <= deg; j += 4) {
        int s0 = src[j + 0], s1 = src[j + 1], s2 = src[j + 2], s3 = src[j + 3];
        float4 v0 = __ldg(hw4 + s0 * 32 + lane);
        float4 v1 = __ldg(hw4 + s1 * 32 + lane);
        float4 v2 = __ldg(hw4 + s2 * 32 + lane);
        float4 v3 = __ldg(hw4 + s3 * 32 + lane);
        acc.x += (v0.x + v1.x) + (v2.x + v3.x);
        acc.y += (v0.y + v1.y) + (v2.y + v3.y);
        acc.z += (v0.z + v1.z) + (v2.z + v3.z);
        acc.w += (v0.w + v1.w) + (v2.w + v3.w);
    }
    for (; j < deg; j++) {
        float4 v = __ldg(hw4 + src[j] * 32 + lane);
        acc.x += v.x; acc.y += v.y; acc.z += v.z; acc.w += v.w;
    }

    float s = g_dinv[node];
    float4 bb = ((const float4*)b)[lane];
    float4 out;
    out.x = fmaf(acc.x, s, bb.x);
    out.y = fmaf(acc.y, s, bb.y);
    out.z = fmaf(acc.z, s, bb.z);
    out.w = fmaf(acc.w, s, bb.w);
    ((float4*)g_agg)[node * 32 + lane] = out;
}

// ---------------------------------------------------------------------------
// GEMM3 (folded): z[i] = dinv[i] * (relu(h2[i]) @ Wfold)   [N,3 in float4]
// ---------------------------------------------------------------------------
__global__ __launch_bounds__(256) void gemm3_kernel(const float* __restrict__ H, int n) {
    __shared__ float4 swf[D];
    const int tid  = threadIdx.x;
    if (tid < D) swf[tid] = g_wfold[tid];
    __syncthreads();

    const int node = blockIdx.x * 8 + (tid >> 5);
    const int lane = tid & 31;
    if (node >= n) return;

    float4 h = *(const float4*)(H + node * D + lane * 4);
    h.x = fmaxf(h.x, 0.f); h.y = fmaxf(h.y, 0.f);
    h.z = fmaxf(h.z, 0.f); h.w = fmaxf(h.w, 0.f);

    float4 w0 = swf[lane * 4 + 0];
    float4 w1 = swf[lane * 4 + 1];
    float4 w2 = swf[lane * 4 + 2];
    float4 w3 = swf[lane * 4 + 3];

    float a0 = h.x * w0.x + h.y * w1.x + h.z * w2.x + h.w * w3.x;
    float a1 = h.x * w0.y + h.y * w1.y + h.z * w2.y + h.w * w3.y;
    float a2 = h.x * w0.z + h.y * w1.z + h.z * w2.z + h.w * w3.z;

#pragma unroll
    for (int m = 16; m > 0; m >>= 1) {
        a0 += __shfl_xor_sync(0xffffffff, a0, m);
        a1 += __shfl_xor_sync(0xffffffff, a1, m);
        a2 += __shfl_xor_sync(0xffffffff, a2, m);
    }
    if (lane == 0) {
        float s = g_dinv[node];
        g_z[node] = make_float4(a0 * s, a1 * s, a2 * s, 0.f);
    }
}

// ---------------------------------------------------------------------------
// gather3: zagg[i] = dinv[i] * (z[i] + sum_in z[src])
// ---------------------------------------------------------------------------
__global__ __launch_bounds__(256) void gather3_kernel(int n) {
    const int node = blockIdx.x * blockDim.x + threadIdx.x;
    if (node >= n) return;

    float4 zv = g_z[node];
    float a0 = zv.x, a1 = zv.y, a2 = zv.z;

    const int off = g_off[node];
    const int deg = g_off[node + 1] - off;
    const int* __restrict__ src = g_srcs + off;

    int j = 0;
    for (; j + 4 <= deg; j += 4) {
        float4 v0 = __ldg(&g_z[src[j + 0]]);
        float4 v1 = __ldg(&g_z[src[j + 1]]);
        float4 v2 = __ldg(&g_z[src[j + 2]]);
        float4 v3 = __ldg(&g_z[src[j + 3]]);
        a0 += (v0.x + v1.x) + (v2.x + v3.x);
        a1 += (v0.y + v1.y) + (v2.y + v3.y);
        a2 += (v0.z + v1.z) + (v2.z + v3.z);
    }
    for (; j < deg; j++) {
        float4 v = __ldg(&g_z[src[j]]);
        a0 += v.x; a1 += v.y; a2 += v.z;
    }
    float s = g_dinv[node];
    g_zagg[node] = make_float4(a0 * s, a1 * s, a2 * s, 0.f);
}

// ---------------------------------------------------------------------------
// pool: out[g] = mean over batch-range of zagg + bfold   (1 warp per graph)
// ---------------------------------------------------------------------------
__global__ __launch_bounds__(32) void pool_kernel(const int* __restrict__ batch,
                                                  float* __restrict__ out, int n) {
    const int g = blockIdx.x;
    const int lane = threadIdx.x;

    int target = g + (lane & 1);
    int lo = 0, hi = n;
    while (lo < hi) {
        int m = (lo + hi) >> 1;
        if (batch[m] < target) lo = m + 1; else hi = m;
    }
    int start = __shfl_sync(0xffffffff, lo, 0);
    int end   = __shfl_sync(0xffffffff, lo, 1);

    float a0 = 0.f, a1 = 0.f, a2 = 0.f;
    for (int i = start + lane; i < end; i += 32) {
        float4 v = g_zagg[i];
        a0 += v.x; a1 += v.y; a2 += v.z;
    }
#pragma unroll
    for (int m = 16; m > 0; m >>= 1) {
        a0 += __shfl_xor_sync(0xffffffff, a0, m);
        a1 += __shfl_xor_sync(0xffffffff, a1, m);
        a2 += __shfl_xor_sync(0xffffffff, a2, m);
    }
    if (lane == 0) {
        float inv = 1.f / fmaxf((float)(end - start), 1.f);
        float4 bf = g_bfold;
        out[g * 3 + 0] = fmaf(a0, inv, bf.x);
        out[g * 3 + 1] = fmaf(a1, inv, bf.y);
        out[g * 3 + 2] = fmaf(a2, inv, bf.z);
    }
}

// ---------------------------------------------------------------------------
// launch
// ---------------------------------------------------------------------------
extern "C" void kernel_launch(void* const* d_in, const int* in_sizes, int n_in,
                              void* d_out, int out_size) {
    const float* x     = (const float*)d_in[0];
    const int*   ei    = (const int*)  d_in[1];
    const int*   batch = (const int*)  d_in[2];
    const float* W1    = (const float*)d_in[3];
    const float* b1    = (const float*)d_in[4];
    const float* W2    = (const float*)d_in[5];
    const float* b2    = (const float*)d_in[6];
    const float* W3    = (const float*)d_in[7];
    const float* b3    = (const float*)d_in[8];
    const float* Wlin  = (const float*)d_in[9];
    const float* blin  = (const float*)d_in[10];
    float* out = (float*)d_out;

    const int n = in_sizes[0] / D;   // 50000
    const int E = in_sizes[1] / 2;   // 800000

    float* hw_ptr;
    cudaGetSymbolAddress((void**)&hw_ptr, g_hw);
    float* agg_ptr;
    cudaGetSymbolAddress((void**)&agg_ptr, g_agg);

    const int gemm_blocks = (n + 31) / 32;
    const int gath_blocks = (n + 7) / 8;

    // CSR build (launch index 3 = gemm<false> -> profiled)
    hist_kernel<<<(E + 255) / 256, 256>>>(ei, E);
    scan_kernel<<<1, 1024>>>(n);
    fill_kernel<<<(E + 255) / 256, 256>>>(ei, E);

    // layer 1
    gemm_kernel<false><<<gemm_blocks, 64>>>(x, W1, hw_ptr, n);
    gather_kernel<<<gath_blocks, 256>>>(b1, n);

    // weight folding for layer 3 (parallel, ~2us)
    fold_kernel<<<D + 1, 32>>>(W3, b3, Wlin, blin);

    // layer 2 (relu fused into GEMM load)
    gemm_kernel<true><<<gemm_blocks, 64>>>(agg_ptr, W2, hw_ptr, n);
    gather_kernel<<<gath_blocks, 256>>>(b2, n);

    // layer 3 folded with head: [N,128] @ [128,3]
    gemm3_kernel<<<gath_blocks, 256>>>(agg_ptr, n);
    gather3_kernel<<<(n + 255) / 256, 256>>>(n);

    // mean pool + bias
    pool_kernel<<<N_GRAPHS, 32>>>(batch, out, n);
}